// round 1
// baseline (speedup 1.0000x reference)
#include <cuda_runtime.h>
#include <math.h>

// Problem constants
#define T_  256
#define B_  64
#define I_  1024
#define L_  2
#define G_  4
#define H_  1024
#define R_  16

#define N_TOT  (G_ * H_)     // 4096 output columns per layer (gate-major)
#define K_HALF 1024          // K of x-part and of h-part

// Split-K GEMM config
#define KS     8             // k-splits: 0..3 -> x/Wx, 4..7 -> h0/Wh
#define KCHUNK 256           // K elements per split
#define BN     64
#define BM     64            // == B_
#define BK     32

// Scratch (allocation-free: __device__ globals)
__device__ float g_pre[KS * N_TOT * B_];       // [ks][n][b], 8 MB
__device__ float g_u[2 * G_ * B_ * R_];        // [src][g][b][r], 32 KB

// ---------------------------------------------------------------------------
// LoRA projections: u[src,g,b,:] = vec[b,:] @ A[l,g,:,:]^T   (K = 1024, R = 16)
// grid = 512 (= 2 src * 4 g * 64 b), block = 256
// ---------------------------------------------------------------------------
__global__ void lora_proj_kernel(const float* __restrict__ x,
                                 const float* __restrict__ h0,
                                 const float* __restrict__ A_x,
                                 const float* __restrict__ A_h,
                                 int l)
{
    int bid = blockIdx.x;
    int src = bid >> 8;            // 0: x, 1: h
    int rem = bid & 255;
    int g   = rem >> 6;
    int b   = rem & 63;

    const float* vec = (src == 0) ? (x + b * I_)
                                  : (h0 + (size_t)l * B_ * H_ + b * H_);
    const float* A   = ((src == 0) ? A_x : A_h) + ((size_t)(l * G_ + g)) * R_ * K_HALF;

    float acc[R_];
#pragma unroll
    for (int r = 0; r < R_; ++r) acc[r] = 0.f;

    for (int i = threadIdx.x; i < K_HALF; i += 256) {
        float v = vec[i];
#pragma unroll
        for (int r = 0; r < R_; ++r)
            acc[r] += v * A[r * K_HALF + i];
    }

    // warp reduce
#pragma unroll
    for (int r = 0; r < R_; ++r) {
#pragma unroll
        for (int off = 16; off > 0; off >>= 1)
            acc[r] += __shfl_down_sync(0xffffffffu, acc[r], off);
    }

    __shared__ float red[8][R_];
    int lane = threadIdx.x & 31, warp = threadIdx.x >> 5;
    if (lane == 0) {
#pragma unroll
        for (int r = 0; r < R_; ++r) red[warp][r] = acc[r];
    }
    __syncthreads();
    if (threadIdx.x < R_) {
        float s = 0.f;
#pragma unroll
        for (int w = 0; w < 8; ++w) s += red[w][threadIdx.x];
        g_u[((size_t)(src * G_ + g) * B_ + b) * R_ + threadIdx.x] = s;
    }
}

// ---------------------------------------------------------------------------
// Main split-K GEMM: g_pre[ks][n][b] = sum_{k in chunk ks} W[n][k] * v[b][k]
//   n = g*1024 + h ; W row for x-part: W_x[(l*4096 + n)*1024 + k]
// grid = (N_TOT/BN = 64, KS = 8), block = 256
// ---------------------------------------------------------------------------
__global__ void __launch_bounds__(256)
gemm_kernel(const float* __restrict__ x,
            const float* __restrict__ h0,
            const float* __restrict__ W_x,
            const float* __restrict__ W_h,
            int l)
{
    const int ks = blockIdx.y;
    const int n0 = blockIdx.x * BN;

    const float* Wbase;
    const float* vbase;
    int koff;
    if (ks < 4) { Wbase = W_x; vbase = x;                              koff = ks * KCHUNK; }
    else        { Wbase = W_h; vbase = h0 + (size_t)l * B_ * H_;       koff = (ks - 4) * KCHUNK; }
    Wbase += (size_t)l * N_TOT * K_HALF;

    __shared__ float Ws[BK][BN + 4];   // [k][n], padded
    __shared__ float Xs[BK][BM + 4];   // [k][b]

    const int tx = threadIdx.x & 15;   // -> 4 b columns
    const int ty = threadIdx.x >> 4;   // -> 4 n rows

    float acc[4][4];
#pragma unroll
    for (int i = 0; i < 4; ++i)
#pragma unroll
        for (int j = 0; j < 4; ++j) acc[i][j] = 0.f;

    for (int kt = 0; kt < KCHUNK; kt += BK) {
#pragma unroll
        for (int it = 0; it < 2; ++it) {
            int idx = threadIdx.x + it * 256;      // 0..511
            int row = idx >> 3;                    // 0..63
            int k4  = idx & 7;                     // 0..7 (float4 along k)
            float4 w = *(const float4*)(Wbase + (size_t)(n0 + row) * K_HALF + koff + kt + k4 * 4);
            Ws[k4 * 4 + 0][row] = w.x;
            Ws[k4 * 4 + 1][row] = w.y;
            Ws[k4 * 4 + 2][row] = w.z;
            Ws[k4 * 4 + 3][row] = w.w;
            float4 xv = *(const float4*)(vbase + (size_t)row * K_HALF + koff + kt + k4 * 4);
            Xs[k4 * 4 + 0][row] = xv.x;
            Xs[k4 * 4 + 1][row] = xv.y;
            Xs[k4 * 4 + 2][row] = xv.z;
            Xs[k4 * 4 + 3][row] = xv.w;
        }
        __syncthreads();

#pragma unroll
        for (int k = 0; k < BK; ++k) {
            float4 wv = *(const float4*)&Ws[k][ty * 4];
            float4 xv = *(const float4*)&Xs[k][tx * 4];
            acc[0][0] += wv.x * xv.x; acc[0][1] += wv.x * xv.y; acc[0][2] += wv.x * xv.z; acc[0][3] += wv.x * xv.w;
            acc[1][0] += wv.y * xv.x; acc[1][1] += wv.y * xv.y; acc[1][2] += wv.y * xv.z; acc[1][3] += wv.y * xv.w;
            acc[2][0] += wv.z * xv.x; acc[2][1] += wv.z * xv.y; acc[2][2] += wv.z * xv.z; acc[2][3] += wv.z * xv.w;
            acc[3][0] += wv.w * xv.x; acc[3][1] += wv.w * xv.y; acc[3][2] += wv.w * xv.z; acc[3][3] += wv.w * xv.w;
        }
        __syncthreads();
    }

#pragma unroll
    for (int i = 0; i < 4; ++i) {
        float4 v = make_float4(acc[i][0], acc[i][1], acc[i][2], acc[i][3]);
        *(float4*)&g_pre[((size_t)ks * N_TOT + n0 + ty * 4 + i) * B_ + tx * 4] = v;
    }
}

// ---------------------------------------------------------------------------
// Gate kernel: sum K-partials + bias + LoRA(rank-16), activations, write out.
// grid = 256 (4 h per block), block = 256 (64 b x 4 h)
// ---------------------------------------------------------------------------
__global__ void gates_kernel(const float* __restrict__ b_x,
                             const float* __restrict__ b_h,
                             const float* __restrict__ B_x,
                             const float* __restrict__ B_h,
                             const float* __restrict__ c0,
                             float* __restrict__ out,
                             int l)
{
    int b  = threadIdx.x & 63;
    int hl = threadIdx.x >> 6;
    int h  = blockIdx.x * 4 + hl;

    float pre[G_];
#pragma unroll
    for (int g = 0; g < G_; ++g) {
        int n = g * H_ + h;
        float s = b_x[(l * G_ + g) * H_ + h] + b_h[(l * G_ + g) * H_ + h];
#pragma unroll
        for (int ks = 0; ks < KS; ++ks)
            s += g_pre[((size_t)ks * N_TOT + n) * B_ + b];

        const float* Bxr = B_x + ((size_t)((l * G_ + g) * H_) + h) * R_;
        const float* uxr = g_u + ((size_t)(0 * G_ + g) * B_ + b) * R_;
        const float* Bhr = B_h + ((size_t)((l * G_ + g) * H_) + h) * R_;
        const float* uhr = g_u + ((size_t)(1 * G_ + g) * B_ + b) * R_;
#pragma unroll
        for (int r = 0; r < R_; ++r) s += Bxr[r] * uxr[r];
#pragma unroll
        for (int r = 0; r < R_; ++r) s += Bhr[r] * uhr[r];
        pre[g] = s;
    }

    float i_t = 1.f / (1.f + expf(-pre[0]));
    float f_t = 1.f / (1.f + expf(-pre[1]));
    float g_t = tanhf(pre[2]);
    float o_t = 1.f / (1.f + expf(-pre[3]));

    float cv   = c0[(size_t)l * B_ * H_ + b * H_ + h];
    float cnew = f_t * cv + i_t * g_t;
    float hnew = o_t * tanhf(cnew);

    size_t idx = (size_t)b * H_ + h;
    out[(size_t)B_ * H_ * (1 + l) + idx] = hnew;   // h_t[l]
    out[(size_t)B_ * H_ * (3 + l) + idx] = cnew;   // c_t[l]
    if (l == 1)
        out[idx] = hnew;                           // out == h_t[1]
}

// ---------------------------------------------------------------------------
extern "C" void kernel_launch(void* const* d_in, const int* in_sizes, int n_in,
                              void* d_out, int out_size)
{
    const float* input_seq = (const float*)d_in[0];
    const float* h0        = (const float*)d_in[1];
    const float* c0        = (const float*)d_in[2];
    const float* W_x       = (const float*)d_in[3];
    const float* W_h       = (const float*)d_in[4];
    const float* b_x       = (const float*)d_in[5];
    const float* b_h       = (const float*)d_in[6];
    const float* A_x       = (const float*)d_in[7];
    const float* B_x       = (const float*)d_in[8];
    const float* A_h       = (const float*)d_in[9];
    const float* B_h       = (const float*)d_in[10];
    float* out = (float*)d_out;

    const float* x_last = input_seq + (size_t)(T_ - 1) * B_ * I_;

    for (int l = 0; l < L_; ++l) {
        const float* x = (l == 0) ? x_last : (out + (size_t)B_ * H_);  // h_t[0]

        lora_proj_kernel<<<512, 256>>>(x, h0, A_x, A_h, l);
        gemm_kernel<<<dim3(N_TOT / BN, KS), 256>>>(x, h0, W_x, W_h, l);
        gates_kernel<<<256, 256>>>(b_x, b_h, B_x, B_h, c0, out, l);
    }
}

// round 3
// speedup vs baseline: 1.4998x; 1.4998x over previous
#include <cuda_runtime.h>
#include <cuda_bf16.h>
#include <math.h>
#include <stdint.h>

// Problem constants
#define T_  256
#define B_  64
#define I_  1024
#define L_  2
#define G_  4
#define H_  1024
#define R_  16

#define N_TOT  (G_ * H_)
#define K_HALF 1024

// GEMM config: grid (32 M-tiles, 4 k-splits), 256 thr
#define KS     4
#define KSLICE 512             // K per split
#define MT     128             // M rows per CTA
#define NSTEP  (KSLICE / 16)   // 32 k16 steps

// Scratch
__device__ float g_pre[KS * N_TOT * B_];   // [ks][m][b]
__device__ float g_u[2 * G_ * B_ * R_];    // [src][g][b][r]

#define SWZ(o) ((o) ^ (((o) >> 3) & 0x70))

__device__ __forceinline__ uint32_t smem_u32(const void* p) {
    uint32_t a;
    asm("{ .reg .u64 t; cvta.to.shared.u64 t, %1; cvt.u32.u64 %0, t; }" : "=r"(a) : "l"(p));
    return a;
}
__device__ __forceinline__ void cvt_hilo(float a, float b, uint32_t& hi, uint32_t& lo) {
    __nv_bfloat162 h = __floats2bfloat162_rn(a, b);
    float ra = a - __bfloat162float(h.x);
    float rb = b - __bfloat162float(h.y);
    __nv_bfloat162 l = __floats2bfloat162_rn(ra, rb);
    hi = *(uint32_t*)&h;
    lo = *(uint32_t*)&l;
}
__device__ __forceinline__ void ldsm4(uint32_t* r, uint32_t addr) {
    asm volatile("ldmatrix.sync.aligned.m8n8.x4.shared.b16 {%0,%1,%2,%3}, [%4];"
                 : "=r"(r[0]), "=r"(r[1]), "=r"(r[2]), "=r"(r[3]) : "r"(addr));
}
__device__ __forceinline__ void mma_bf16(float* d, const uint32_t* a, uint32_t b0, uint32_t b1) {
    asm volatile("mma.sync.aligned.m16n8k16.row.col.f32.bf16.bf16.f32 "
                 "{%0,%1,%2,%3}, {%4,%5,%6,%7}, {%8,%9}, {%0,%1,%2,%3};"
                 : "+f"(d[0]), "+f"(d[1]), "+f"(d[2]), "+f"(d[3])
                 : "r"(a[0]), "r"(a[1]), "r"(a[2]), "r"(a[3]), "r"(b0), "r"(b1));
}

// ---------------------------------------------------------------------------
// HMMA split-K GEMM, bf16 3-term split precision, fp32 accumulate.
// g_pre[ks][m][b] = sum_k W[m][k] * v[b][k]  over this split's K range.
// ---------------------------------------------------------------------------
__global__ void __launch_bounds__(256)
gemm_mma_kernel(const float* __restrict__ x, const float* __restrict__ h0,
                const float* __restrict__ W_x, const float* __restrict__ W_h, int l)
{
    __shared__ __align__(1024) uint8_t sx_hi[8192];   // x chunk: 64 n x 64 k bf16, SWZ
    __shared__ __align__(1024) uint8_t sx_lo[8192];

    const int tid  = threadIdx.x;
    const int wid  = tid >> 5;
    const int lane = tid & 31;
    const int ks   = blockIdx.y;
    const int m0   = blockIdx.x * MT;

    const float* Wbase;
    const float* vbase;
    int koff;
    if (ks < 2) { Wbase = W_x + (size_t)l * N_TOT * K_HALF; vbase = x;
                  koff = ks * KSLICE; }
    else        { Wbase = W_h + (size_t)l * N_TOT * K_HALF; vbase = h0 + (size_t)l * B_ * H_;
                  koff = (ks - 2) * KSLICE; }

    const int g = lane >> 2;       // fragment row group
    const int q = lane & 3;        // fragment col group

    // W pointers for this warp's 16-row slice
    const float* WA = Wbase + (size_t)(m0 + wid * 16 + g) * K_HALF + koff;
    const float* WB = WA + 8 * (size_t)K_HALF;

    // x staging geometry: thread -> (row n, quarter of 64-k chunk)
    const int xn = tid >> 2;
    const int xq = tid & 3;
    const float* Xsrc = vbase + (size_t)xn * K_HALF + koff + xq * 16;
    uint32_t st_off[4];
#pragma unroll
    for (int j = 0; j < 4; ++j) {
        uint32_t o = (uint32_t)xn * 128u + (uint32_t)xq * 32u + (uint32_t)j * 8u;
        st_off[j] = SWZ(o);
    }

    // ldmatrix lane geometry (x4: m0=(t,k0) m1=(t,k8) m2=(t+1,k0) m3=(t+1,k8))
    const int lm_row  = 8 * ((lane >> 4) & 1) + (lane & 7);
    const int lm_kb   = ((lane >> 3) & 1) * 16;
    const int cswz    = (lane & 7) << 4;
    const uint32_t rowoff = (uint32_t)lm_row * 128u;
    const uint32_t hi_base = smem_u32(sx_hi);
    const uint32_t lo_base = smem_u32(sx_lo);

    float acc[8][4];
#pragma unroll
    for (int t = 0; t < 8; ++t)
#pragma unroll
        for (int j = 0; j < 4; ++j) acc[t][j] = 0.f;

    // preload step 0 W fragments
    float2 wA0, wA1, wB0, wB1;
    {
        const int kk = 2 * q;
        wA0 = *(const float2*)(WA + kk);
        wA1 = *(const float2*)(WA + kk + 8);
        wB0 = *(const float2*)(WB + kk);
        wB1 = *(const float2*)(WB + kk + 8);
    }

#pragma unroll 1
    for (int step = 0; step < NSTEP; ++step) {
        if ((step & 3) == 0) {                 // stage next 64-k chunk of x
            if (step) __syncthreads();
            const float4* s4 = (const float4*)(Xsrc + (step >> 2) * 64);
#pragma unroll
            for (int j = 0; j < 4; ++j) {
                float4 f = s4[j];
                uint32_t h01, l01, h23, l23;
                cvt_hilo(f.x, f.y, h01, l01);
                cvt_hilo(f.z, f.w, h23, l23);
                *(uint2*)(sx_hi + st_off[j]) = make_uint2(h01, h23);
                *(uint2*)(sx_lo + st_off[j]) = make_uint2(l01, l23);
            }
            __syncthreads();
        }

        // convert A fragments (W) to bf16 hi/lo
        uint32_t a_hi[4], a_lo[4];
        cvt_hilo(wA0.x, wA0.y, a_hi[0], a_lo[0]);
        cvt_hilo(wB0.x, wB0.y, a_hi[1], a_lo[1]);
        cvt_hilo(wA1.x, wA1.y, a_hi[2], a_lo[2]);
        cvt_hilo(wB1.x, wB1.y, a_hi[3], a_lo[3]);

        // prefetch next step's W fragments
        if (step + 1 < NSTEP) {
            const int kk = (step + 1) * 16 + 2 * q;
            wA0 = *(const float2*)(WA + kk);
            wA1 = *(const float2*)(WA + kk + 8);
            wB0 = *(const float2*)(WB + kk);
            wB1 = *(const float2*)(WB + kk + 8);
        }

        const int kb = lm_kb + (step & 3) * 32;
        const uint32_t koffsw = (uint32_t)(kb ^ cswz);

#pragma unroll
        for (int tp = 0; tp < 4; ++tp) {
            const uint32_t off = rowoff + (uint32_t)tp * 2048u + koffsw;
            uint32_t bh[4], bl[4];
            ldsm4(bh, hi_base + off);
            ldsm4(bl, lo_base + off);
            // n-tile 2*tp
            mma_bf16(acc[2 * tp],     a_hi, bh[0], bh[1]);
            mma_bf16(acc[2 * tp],     a_hi, bl[0], bl[1]);
            mma_bf16(acc[2 * tp],     a_lo, bh[0], bh[1]);
            // n-tile 2*tp+1
            mma_bf16(acc[2 * tp + 1], a_hi, bh[2], bh[3]);
            mma_bf16(acc[2 * tp + 1], a_hi, bl[2], bl[3]);
            mma_bf16(acc[2 * tp + 1], a_lo, bh[2], bh[3]);
        }
    }

    // epilogue: acc[t][0,1] -> row (m0+wid*16+g), b = 8t+2q ; acc[t][2,3] -> row +8
    float* base0 = &g_pre[((size_t)ks * N_TOT + m0 + wid * 16 + g) * B_];
    float* base8 = base0 + 8 * B_;
#pragma unroll
    for (int t = 0; t < 8; ++t) {
        *(float2*)(base0 + t * 8 + 2 * q) = make_float2(acc[t][0], acc[t][1]);
        *(float2*)(base8 + t * 8 + 2 * q) = make_float2(acc[t][2], acc[t][3]);
    }
}

// ---------------------------------------------------------------------------
// LoRA projections: u[src,g,b,:] = vec[b,:] @ A[l,g,:,:]^T  (warp per 2 ranks)
// ---------------------------------------------------------------------------
__global__ void lora_proj_kernel(const float* __restrict__ x,
                                 const float* __restrict__ h0,
                                 const float* __restrict__ A_x,
                                 const float* __restrict__ A_h,
                                 int l)
{
    const int bid = blockIdx.x;
    const int src = bid >> 8;
    const int rem = bid & 255;
    const int g   = rem >> 6;
    const int b   = rem & 63;
    const int wid = threadIdx.x >> 5, lid = threadIdx.x & 31;

    const float* vec = (src == 0) ? (x + (size_t)b * I_)
                                  : (h0 + (size_t)l * B_ * H_ + (size_t)b * H_);
    const float* A = ((src == 0) ? A_x : A_h) + ((size_t)(l * G_ + g)) * R_ * K_HALF;

    const float4* v4 = (const float4*)vec;
    const float4* a0 = (const float4*)(A + (size_t)(wid * 2) * K_HALF);
    const float4* a1 = (const float4*)(A + (size_t)(wid * 2 + 1) * K_HALF);

    float acc0 = 0.f, acc1 = 0.f;
#pragma unroll
    for (int j = 0; j < 8; ++j) {
        const int i4 = j * 32 + lid;
        float4 v = v4[i4];
        float4 a = a0[i4];
        float4 c = a1[i4];
        acc0 += v.x * a.x + v.y * a.y + v.z * a.z + v.w * a.w;
        acc1 += v.x * c.x + v.y * c.y + v.z * c.z + v.w * c.w;
    }
#pragma unroll
    for (int off = 16; off > 0; off >>= 1) {
        acc0 += __shfl_down_sync(0xffffffffu, acc0, off);
        acc1 += __shfl_down_sync(0xffffffffu, acc1, off);
    }
    if (lid == 0) {
        float* u = &g_u[((size_t)(src * G_ + g) * B_ + b) * R_];
        u[wid * 2]     = acc0;
        u[wid * 2 + 1] = acc1;
    }
}

// ---------------------------------------------------------------------------
// Gates: sum K-partials + bias + rank-16 LoRA, activations, write outputs.
// ---------------------------------------------------------------------------
__global__ void gates_kernel(const float* __restrict__ b_x,
                             const float* __restrict__ b_h,
                             const float* __restrict__ B_x,
                             const float* __restrict__ B_h,
                             const float* __restrict__ c0,
                             float* __restrict__ out,
                             int l)
{
    const int b  = threadIdx.x & 63;
    const int hl = threadIdx.x >> 6;
    const int h  = blockIdx.x * 4 + hl;

    float pre[G_];
#pragma unroll
    for (int g = 0; g < G_; ++g) {
        const int n = g * H_ + h;
        float s = b_x[(l * G_ + g) * H_ + h] + b_h[(l * G_ + g) * H_ + h];
#pragma unroll
        for (int ks = 0; ks < KS; ++ks)
            s += g_pre[((size_t)ks * N_TOT + n) * B_ + b];

        const float* Bxr = B_x + ((size_t)((l * G_ + g) * H_) + h) * R_;
        const float* uxr = g_u + ((size_t)(0 * G_ + g) * B_ + b) * R_;
        const float* Bhr = B_h + ((size_t)((l * G_ + g) * H_) + h) * R_;
        const float* uhr = g_u + ((size_t)(1 * G_ + g) * B_ + b) * R_;
#pragma unroll
        for (int r = 0; r < R_; ++r) s += Bxr[r] * uxr[r];
#pragma unroll
        for (int r = 0; r < R_; ++r) s += Bhr[r] * uhr[r];
        pre[g] = s;
    }

    const float i_t = 1.f / (1.f + expf(-pre[0]));
    const float f_t = 1.f / (1.f + expf(-pre[1]));
    const float g_t = tanhf(pre[2]);
    const float o_t = 1.f / (1.f + expf(-pre[3]));

    const float cv   = c0[(size_t)l * B_ * H_ + (size_t)b * H_ + h];
    const float cnew = f_t * cv + i_t * g_t;
    const float hnew = o_t * tanhf(cnew);

    const size_t idx = (size_t)b * H_ + h;
    out[(size_t)B_ * H_ * (1 + l) + idx] = hnew;   // h_t[l]
    out[(size_t)B_ * H_ * (3 + l) + idx] = cnew;   // c_t[l]
    if (l == 1)
        out[idx] = hnew;                           // out == h_t[1]
}

// ---------------------------------------------------------------------------
extern "C" void kernel_launch(void* const* d_in, const int* in_sizes, int n_in,
                              void* d_out, int out_size)
{
    const float* input_seq = (const float*)d_in[0];
    const float* h0        = (const float*)d_in[1];
    const float* c0        = (const float*)d_in[2];
    const float* W_x       = (const float*)d_in[3];
    const float* W_h       = (const float*)d_in[4];
    const float* b_x       = (const float*)d_in[5];
    const float* b_h       = (const float*)d_in[6];
    const float* A_x       = (const float*)d_in[7];
    const float* B_x       = (const float*)d_in[8];
    const float* A_h       = (const float*)d_in[9];
    const float* B_h       = (const float*)d_in[10];
    float* out = (float*)d_out;

    const float* x_last = input_seq + (size_t)(T_ - 1) * B_ * I_;

    for (int l = 0; l < L_; ++l) {
        const float* x = (l == 0) ? x_last : (out + (size_t)B_ * H_);  // h_t[0]

        gemm_mma_kernel<<<dim3(N_TOT / MT, KS), 256>>>(x, h0, W_x, W_h, l);
        lora_proj_kernel<<<512, 256>>>(x, h0, A_x, A_h, l);
        gates_kernel<<<256, 256>>>(b_x, b_h, B_x, B_h, c0, out, l);
    }
}

// round 4
// speedup vs baseline: 1.5885x; 1.0591x over previous
#include <cuda_runtime.h>
#include <cuda_bf16.h>
#include <math.h>
#include <stdint.h>

// Problem constants
#define T_  256
#define B_  64
#define I_  1024
#define L_  2
#define G_  4
#define H_  1024
#define R_  16

#define N_TOT  (G_ * H_)
#define K_HALF 1024

// GEMM config: grid (32 M-tiles, 8 k-splits), 256 thr, 2 CTA/SM
#define KS     8
#define KSLICE 256             // K per split
#define MT     128             // M rows per CTA
#define NSTEP  (KSLICE / 16)   // 16 k16 steps

// Scratch
__device__ float g_pre[KS * N_TOT * B_];   // [ks][m][b]  8 MB
__device__ float g_u[2 * G_ * B_ * R_];    // [src][g][b][r]

#define SWZ(o) ((o) ^ (((o) >> 3) & 0x70))

__device__ __forceinline__ uint32_t smem_u32(const void* p) {
    uint32_t a;
    asm("{ .reg .u64 t; cvta.to.shared.u64 t, %1; cvt.u32.u64 %0, t; }" : "=r"(a) : "l"(p));
    return a;
}
__device__ __forceinline__ void cvt_hilo(float a, float b, uint32_t& hi, uint32_t& lo) {
    __nv_bfloat162 h = __floats2bfloat162_rn(a, b);
    float ra = a - __bfloat162float(h.x);
    float rb = b - __bfloat162float(h.y);
    __nv_bfloat162 l = __floats2bfloat162_rn(ra, rb);
    hi = *(uint32_t*)&h;
    lo = *(uint32_t*)&l;
}
__device__ __forceinline__ void ldsm4(uint32_t* r, uint32_t addr) {
    asm volatile("ldmatrix.sync.aligned.m8n8.x4.shared.b16 {%0,%1,%2,%3}, [%4];"
                 : "=r"(r[0]), "=r"(r[1]), "=r"(r[2]), "=r"(r[3]) : "r"(addr));
}
__device__ __forceinline__ void mma_bf16(float* d, const uint32_t* a, uint32_t b0, uint32_t b1) {
    asm volatile("mma.sync.aligned.m16n8k16.row.col.f32.bf16.bf16.f32 "
                 "{%0,%1,%2,%3}, {%4,%5,%6,%7}, {%8,%9}, {%0,%1,%2,%3};"
                 : "+f"(d[0]), "+f"(d[1]), "+f"(d[2]), "+f"(d[3])
                 : "r"(a[0]), "r"(a[1]), "r"(a[2]), "r"(a[3]), "r"(b0), "r"(b1));
}

// ---------------------------------------------------------------------------
// Fused kernel: (a) rank-16 LoRA projections (2 warp-tasks per warp, up front,
// hidden under the W DRAM stream), (b) HMMA split-K GEMM with bf16 3-term
// split precision and 2-deep W register prefetch.
// ---------------------------------------------------------------------------
__global__ void __launch_bounds__(256, 2)
gemm_mma_kernel(const float* __restrict__ x, const float* __restrict__ h0,
                const float* __restrict__ W_x, const float* __restrict__ W_h,
                const float* __restrict__ A_x, const float* __restrict__ A_h,
                int l)
{
    __shared__ __align__(1024) uint8_t sx_hi[8192];   // x chunk: 64 n x 64 k bf16, SWZ
    __shared__ __align__(1024) uint8_t sx_lo[8192];

    const int tid  = threadIdx.x;
    const int wid  = tid >> 5;
    const int lane = tid & 31;
    const int ks   = blockIdx.y;
    const int m0   = blockIdx.x * MT;

    const float* Wbase;
    const float* vbase;
    int koff;
    if (ks < 4) { Wbase = W_x + (size_t)l * N_TOT * K_HALF; vbase = x;
                  koff = ks * KSLICE; }
    else        { Wbase = W_h + (size_t)l * N_TOT * K_HALF; vbase = h0 + (size_t)l * B_ * H_;
                  koff = (ks - 4) * KSLICE; }

    const int g = lane >> 2;       // fragment row group
    const int q = lane & 3;        // fragment col group

    const float* WA = Wbase + (size_t)(m0 + wid * 16 + g) * K_HALF + koff;
    const float* WB = WA + 8 * (size_t)K_HALF;

    // -------- issue first two steps of W loads immediately (2-deep) --------
    float2 wbufA0[2], wbufA1[2], wbufB0[2], wbufB1[2];
#pragma unroll
    for (int s = 0; s < 2; ++s) {
        const int kk = s * 16 + 2 * q;
        wbufA0[s] = *(const float2*)(WA + kk);
        wbufA1[s] = *(const float2*)(WA + kk + 8);
        wbufB0[s] = *(const float2*)(WB + kk);
        wbufB1[s] = *(const float2*)(WB + kk + 8);
    }

    // -------- LoRA projections (done while W loads are in flight) --------
    {
        const uint32_t wg = ((uint32_t)blockIdx.y * 32u + blockIdx.x) * 8u + wid;
#pragma unroll
        for (int t = 0; t < 2; ++t) {
            const uint32_t task = wg * 2u + t;      // 0..4095
            const int src  = task >> 11;
            const int rem  = task & 2047;
            const int gg   = rem >> 9;
            const int rem2 = rem & 511;
            const int b    = rem2 >> 3;
            const int rp   = rem2 & 7;

            const float* vec = (src == 0) ? (x + (size_t)b * I_)
                                          : (h0 + (size_t)l * B_ * H_ + (size_t)b * H_);
            const float* A = ((src == 0) ? A_x : A_h) + ((size_t)(l * G_ + gg)) * R_ * K_HALF;
            const float4* v4 = (const float4*)vec;
            const float4* a0 = (const float4*)(A + (size_t)(rp * 2) * K_HALF);
            const float4* a1 = (const float4*)(A + (size_t)(rp * 2 + 1) * K_HALF);

            float acc0 = 0.f, acc1 = 0.f;
#pragma unroll
            for (int j = 0; j < 8; ++j) {
                const int i4 = j * 32 + lane;
                float4 v = v4[i4];
                float4 a = a0[i4];
                float4 c = a1[i4];
                acc0 += v.x * a.x + v.y * a.y + v.z * a.z + v.w * a.w;
                acc1 += v.x * c.x + v.y * c.y + v.z * c.z + v.w * c.w;
            }
#pragma unroll
            for (int off = 16; off > 0; off >>= 1) {
                acc0 += __shfl_down_sync(0xffffffffu, acc0, off);
                acc1 += __shfl_down_sync(0xffffffffu, acc1, off);
            }
            if (lane == 0) {
                float* u = &g_u[((size_t)(src * G_ + gg) * B_ + b) * R_];
                u[rp * 2]     = acc0;
                u[rp * 2 + 1] = acc1;
            }
        }
    }

    // -------- x staging geometry --------
    const int xn = tid >> 2;
    const int xq = tid & 3;
    const float* Xsrc = vbase + (size_t)xn * K_HALF + koff + xq * 16;
    uint32_t st_off[4];
#pragma unroll
    for (int j = 0; j < 4; ++j) {
        uint32_t o = (uint32_t)xn * 128u + (uint32_t)xq * 32u + (uint32_t)j * 8u;
        st_off[j] = SWZ(o);
    }

    // ldmatrix lane geometry
    const int lm_row  = 8 * ((lane >> 4) & 1) + (lane & 7);
    const int lm_kb   = ((lane >> 3) & 1) * 16;
    const int cswz    = (lane & 7) << 4;
    const uint32_t rowoff = (uint32_t)lm_row * 128u;
    const uint32_t hi_base = smem_u32(sx_hi);
    const uint32_t lo_base = smem_u32(sx_lo);

    float acc[8][4];
#pragma unroll
    for (int t = 0; t < 8; ++t)
#pragma unroll
        for (int j = 0; j < 4; ++j) acc[t][j] = 0.f;

#pragma unroll 1
    for (int step = 0; step < NSTEP; ++step) {
        if ((step & 3) == 0) {                 // stage next 64-k chunk of x
            if (step) __syncthreads();
            const float4* s4 = (const float4*)(Xsrc + (step >> 2) * 64);
#pragma unroll
            for (int j = 0; j < 4; ++j) {
                float4 f = s4[j];
                uint32_t h01, l01, h23, l23;
                cvt_hilo(f.x, f.y, h01, l01);
                cvt_hilo(f.z, f.w, h23, l23);
                *(uint2*)(sx_hi + st_off[j]) = make_uint2(h01, h23);
                *(uint2*)(sx_lo + st_off[j]) = make_uint2(l01, l23);
            }
            __syncthreads();
        }

        const int cur = step & 1;

        // convert A fragments (W) to bf16 hi/lo
        uint32_t a_hi[4], a_lo[4];
        cvt_hilo(wbufA0[cur].x, wbufA0[cur].y, a_hi[0], a_lo[0]);
        cvt_hilo(wbufB0[cur].x, wbufB0[cur].y, a_hi[1], a_lo[1]);
        cvt_hilo(wbufA1[cur].x, wbufA1[cur].y, a_hi[2], a_lo[2]);
        cvt_hilo(wbufB1[cur].x, wbufB1[cur].y, a_hi[3], a_lo[3]);

        // prefetch step+2's W fragments into the slot just freed
        if (step + 2 < NSTEP) {
            const int kk = (step + 2) * 16 + 2 * q;
            wbufA0[cur] = *(const float2*)(WA + kk);
            wbufA1[cur] = *(const float2*)(WA + kk + 8);
            wbufB0[cur] = *(const float2*)(WB + kk);
            wbufB1[cur] = *(const float2*)(WB + kk + 8);
        }

        const int kb = lm_kb + (step & 3) * 32;
        const uint32_t koffsw = (uint32_t)(kb ^ cswz);

#pragma unroll
        for (int tp = 0; tp < 4; ++tp) {
            const uint32_t off = rowoff + (uint32_t)tp * 2048u + koffsw;
            uint32_t bh[4], bl[4];
            ldsm4(bh, hi_base + off);
            ldsm4(bl, lo_base + off);
            mma_bf16(acc[2 * tp],     a_hi, bh[0], bh[1]);
            mma_bf16(acc[2 * tp],     a_hi, bl[0], bl[1]);
            mma_bf16(acc[2 * tp],     a_lo, bh[0], bh[1]);
            mma_bf16(acc[2 * tp + 1], a_hi, bh[2], bh[3]);
            mma_bf16(acc[2 * tp + 1], a_hi, bl[2], bl[3]);
            mma_bf16(acc[2 * tp + 1], a_lo, bh[2], bh[3]);
        }
    }

    // epilogue
    float* base0 = &g_pre[((size_t)ks * N_TOT + m0 + wid * 16 + g) * B_];
    float* base8 = base0 + 8 * B_;
#pragma unroll
    for (int t = 0; t < 8; ++t) {
        *(float2*)(base0 + t * 8 + 2 * q) = make_float2(acc[t][0], acc[t][1]);
        *(float2*)(base8 + t * 8 + 2 * q) = make_float2(acc[t][2], acc[t][3]);
    }
}

// ---------------------------------------------------------------------------
// Gates: sum 8 K-partials + bias + rank-16 LoRA, activations, write outputs.
// ---------------------------------------------------------------------------
__global__ void gates_kernel(const float* __restrict__ b_x,
                             const float* __restrict__ b_h,
                             const float* __restrict__ B_x,
                             const float* __restrict__ B_h,
                             const float* __restrict__ c0,
                             float* __restrict__ out,
                             int l)
{
    const int b  = threadIdx.x & 63;
    const int hl = threadIdx.x >> 6;
    const int h  = blockIdx.x * 4 + hl;

    float pre[G_];
#pragma unroll
    for (int g = 0; g < G_; ++g) {
        const int n = g * H_ + h;
        float s = b_x[(l * G_ + g) * H_ + h] + b_h[(l * G_ + g) * H_ + h];
#pragma unroll
        for (int ks = 0; ks < KS; ++ks)
            s += g_pre[((size_t)ks * N_TOT + n) * B_ + b];

        const float* Bxr = B_x + ((size_t)((l * G_ + g) * H_) + h) * R_;
        const float* uxr = g_u + ((size_t)(0 * G_ + g) * B_ + b) * R_;
        const float* Bhr = B_h + ((size_t)((l * G_ + g) * H_) + h) * R_;
        const float* uhr = g_u + ((size_t)(1 * G_ + g) * B_ + b) * R_;
#pragma unroll
        for (int r = 0; r < R_; ++r) s += Bxr[r] * uxr[r];
#pragma unroll
        for (int r = 0; r < R_; ++r) s += Bhr[r] * uhr[r];
        pre[g] = s;
    }

    const float i_t = 1.f / (1.f + expf(-pre[0]));
    const float f_t = 1.f / (1.f + expf(-pre[1]));
    const float g_t = tanhf(pre[2]);
    const float o_t = 1.f / (1.f + expf(-pre[3]));

    const float cv   = c0[(size_t)l * B_ * H_ + (size_t)b * H_ + h];
    const float cnew = f_t * cv + i_t * g_t;
    const float hnew = o_t * tanhf(cnew);

    const size_t idx = (size_t)b * H_ + h;
    out[(size_t)B_ * H_ * (1 + l) + idx] = hnew;   // h_t[l]
    out[(size_t)B_ * H_ * (3 + l) + idx] = cnew;   // c_t[l]
    if (l == 1)
        out[idx] = hnew;                           // out == h_t[1]
}

// ---------------------------------------------------------------------------
extern "C" void kernel_launch(void* const* d_in, const int* in_sizes, int n_in,
                              void* d_out, int out_size)
{
    const float* input_seq = (const float*)d_in[0];
    const float* h0        = (const float*)d_in[1];
    const float* c0        = (const float*)d_in[2];
    const float* W_x       = (const float*)d_in[3];
    const float* W_h       = (const float*)d_in[4];
    const float* b_x       = (const float*)d_in[5];
    const float* b_h       = (const float*)d_in[6];
    const float* A_x       = (const float*)d_in[7];
    const float* B_x       = (const float*)d_in[8];
    const float* A_h       = (const float*)d_in[9];
    const float* B_h       = (const float*)d_in[10];
    float* out = (float*)d_out;

    const float* x_last = input_seq + (size_t)(T_ - 1) * B_ * I_;

    for (int l = 0; l < L_; ++l) {
        const float* x = (l == 0) ? x_last : (out + (size_t)B_ * H_);  // h_t[0]

        gemm_mma_kernel<<<dim3(N_TOT / MT, KS), 256>>>(x, h0, W_x, W_h, A_x, A_h, l);
        gates_kernel<<<256, 256>>>(b_x, b_h, B_x, B_h, c0, out, l);
    }
}

// round 5
// speedup vs baseline: 2.4162x; 1.5211x over previous
#include <cuda_runtime.h>
#include <cuda_bf16.h>
#include <math.h>
#include <stdint.h>

// Problem constants
#define T_  256
#define B_  64
#define I_  1024
#define L_  2
#define G_  4
#define H_  1024
#define R_  16

#define N_TOT  (G_ * H_)
#define K_HALF 1024

// GEMM config: grid (32 M-tiles, 8 k-splits), 256 thr, 2 CTA/SM
#define KS     8
#define KSLICE 256             // K per split
#define MT     128             // M rows per CTA
#define NSTEP  (KSLICE / 16)   // 16 k16 steps
#define PF     3               // W prefetch depth

// Scratch
__device__ float g_pre[KS * N_TOT * B_];   // [ks][m][b]  8 MB
__device__ float g_u[2 * G_ * B_ * R_];    // [src][g][b][r]

#define SWZ(o) ((o) ^ (((o) >> 3) & 0x70))

__device__ __forceinline__ uint32_t smem_u32(const void* p) {
    uint32_t a;
    asm("{ .reg .u64 t; cvta.to.shared.u64 t, %1; cvt.u32.u64 %0, t; }" : "=r"(a) : "l"(p));
    return a;
}
__device__ __forceinline__ void cvt_hilo(float a, float b, uint32_t& hi, uint32_t& lo) {
    __nv_bfloat162 h = __floats2bfloat162_rn(a, b);
    float ra = a - __bfloat162float(h.x);
    float rb = b - __bfloat162float(h.y);
    __nv_bfloat162 l = __floats2bfloat162_rn(ra, rb);
    hi = *(uint32_t*)&h;
    lo = *(uint32_t*)&l;
}
__device__ __forceinline__ void ldsm4(uint32_t* r, uint32_t addr) {
    asm volatile("ldmatrix.sync.aligned.m8n8.x4.shared.b16 {%0,%1,%2,%3}, [%4];"
                 : "=r"(r[0]), "=r"(r[1]), "=r"(r[2]), "=r"(r[3]) : "r"(addr));
}
__device__ __forceinline__ void mma_bf16(float* d, const uint32_t* a, uint32_t b0, uint32_t b1) {
    asm volatile("mma.sync.aligned.m16n8k16.row.col.f32.bf16.bf16.f32 "
                 "{%0,%1,%2,%3}, {%4,%5,%6,%7}, {%8,%9}, {%0,%1,%2,%3};"
                 : "+f"(d[0]), "+f"(d[1]), "+f"(d[2]), "+f"(d[3])
                 : "r"(a[0]), "r"(a[1]), "r"(a[2]), "r"(a[3]), "r"(b0), "r"(b1));
}

// ---------------------------------------------------------------------------
// Fused kernel: (a) rank-16 LoRA projections (hidden under the W stream),
// (b) HMMA split-K GEMM, bf16 3-term split precision, 3-deep W prefetch.
// ---------------------------------------------------------------------------
__global__ void __launch_bounds__(256, 2)
gemm_mma_kernel(const float* __restrict__ x, const float* __restrict__ h0,
                const float* __restrict__ W_x, const float* __restrict__ W_h,
                const float* __restrict__ A_x, const float* __restrict__ A_h,
                int l)
{
    __shared__ __align__(1024) uint8_t sx_hi[8192];   // x chunk: 64 n x 64 k bf16, SWZ
    __shared__ __align__(1024) uint8_t sx_lo[8192];

    const int tid  = threadIdx.x;
    const int wid  = tid >> 5;
    const int lane = tid & 31;
    const int ks   = blockIdx.y;
    const int m0   = blockIdx.x * MT;

    const float* Wbase;
    const float* vbase;
    int koff;
    if (ks < 4) { Wbase = W_x + (size_t)l * N_TOT * K_HALF; vbase = x;
                  koff = ks * KSLICE; }
    else        { Wbase = W_h + (size_t)l * N_TOT * K_HALF; vbase = h0 + (size_t)l * B_ * H_;
                  koff = (ks - 4) * KSLICE; }

    const int g = lane >> 2;
    const int q = lane & 3;

    const float* WA = Wbase + (size_t)(m0 + wid * 16 + g) * K_HALF + koff;
    const float* WB = WA + 8 * (size_t)K_HALF;

    // -------- issue first PF steps of W loads immediately --------
    float2 wbufA0[PF], wbufA1[PF], wbufB0[PF], wbufB1[PF];
#pragma unroll
    for (int s = 0; s < PF; ++s) {
        const int kk = s * 16 + 2 * q;
        wbufA0[s] = *(const float2*)(WA + kk);
        wbufA1[s] = *(const float2*)(WA + kk + 8);
        wbufB0[s] = *(const float2*)(WB + kk);
        wbufB1[s] = *(const float2*)(WB + kk + 8);
    }

    // -------- LoRA projections (while W loads are in flight) --------
    {
        const uint32_t wg = ((uint32_t)blockIdx.y * 32u + blockIdx.x) * 8u + wid;
#pragma unroll
        for (int t = 0; t < 2; ++t) {
            const uint32_t task = wg * 2u + t;      // 0..4095
            const int src  = task >> 11;
            const int rem  = task & 2047;
            const int gg   = rem >> 9;
            const int rem2 = rem & 511;
            const int b    = rem2 >> 3;
            const int rp   = rem2 & 7;

            const float* vec = (src == 0) ? (x + (size_t)b * I_)
                                          : (h0 + (size_t)l * B_ * H_ + (size_t)b * H_);
            const float* A = ((src == 0) ? A_x : A_h) + ((size_t)(l * G_ + gg)) * R_ * K_HALF;
            const float4* v4 = (const float4*)vec;
            const float4* a0 = (const float4*)(A + (size_t)(rp * 2) * K_HALF);
            const float4* a1 = (const float4*)(A + (size_t)(rp * 2 + 1) * K_HALF);

            float acc0 = 0.f, acc1 = 0.f;
#pragma unroll
            for (int j = 0; j < 8; ++j) {
                const int i4 = j * 32 + lane;
                float4 v = v4[i4];
                float4 a = a0[i4];
                float4 c = a1[i4];
                acc0 += v.x * a.x + v.y * a.y + v.z * a.z + v.w * a.w;
                acc1 += v.x * c.x + v.y * c.y + v.z * c.z + v.w * c.w;
            }
#pragma unroll
            for (int off = 16; off > 0; off >>= 1) {
                acc0 += __shfl_down_sync(0xffffffffu, acc0, off);
                acc1 += __shfl_down_sync(0xffffffffu, acc1, off);
            }
            if (lane == 0) {
                float* u = &g_u[((size_t)(src * G_ + gg) * B_ + b) * R_];
                u[rp * 2]     = acc0;
                u[rp * 2 + 1] = acc1;
            }
        }
    }

    // -------- x staging geometry --------
    const int xn = tid >> 2;
    const int xq = tid & 3;
    const float* Xsrc = vbase + (size_t)xn * K_HALF + koff + xq * 16;
    uint32_t st_off[4];
#pragma unroll
    for (int j = 0; j < 4; ++j) {
        uint32_t o = (uint32_t)xn * 128u + (uint32_t)xq * 32u + (uint32_t)j * 8u;
        st_off[j] = SWZ(o);
    }

    // ldmatrix lane geometry
    const int lm_row  = 8 * ((lane >> 4) & 1) + (lane & 7);
    const int lm_kb   = ((lane >> 3) & 1) * 16;
    const int cswz    = (lane & 7) << 4;
    const uint32_t rowoff = (uint32_t)lm_row * 128u;
    const uint32_t hi_base = smem_u32(sx_hi);
    const uint32_t lo_base = smem_u32(sx_lo);

    float acc[8][4];
#pragma unroll
    for (int t = 0; t < 8; ++t)
#pragma unroll
        for (int j = 0; j < 4; ++j) acc[t][j] = 0.f;

#pragma unroll
    for (int step = 0; step < NSTEP; ++step) {
        if ((step & 3) == 0) {                 // stage next 64-k chunk of x
            if (step) __syncthreads();
            const float4* s4 = (const float4*)(Xsrc + (step >> 2) * 64);
#pragma unroll
            for (int j = 0; j < 4; ++j) {
                float4 f = s4[j];
                uint32_t h01, l01, h23, l23;
                cvt_hilo(f.x, f.y, h01, l01);
                cvt_hilo(f.z, f.w, h23, l23);
                *(uint2*)(sx_hi + st_off[j]) = make_uint2(h01, h23);
                *(uint2*)(sx_lo + st_off[j]) = make_uint2(l01, l23);
            }
            __syncthreads();
        }

        const int cur = step % PF;             // static under full unroll

        uint32_t a_hi[4], a_lo[4];
        cvt_hilo(wbufA0[cur].x, wbufA0[cur].y, a_hi[0], a_lo[0]);
        cvt_hilo(wbufB0[cur].x, wbufB0[cur].y, a_hi[1], a_lo[1]);
        cvt_hilo(wbufA1[cur].x, wbufA1[cur].y, a_hi[2], a_lo[2]);
        cvt_hilo(wbufB1[cur].x, wbufB1[cur].y, a_hi[3], a_lo[3]);

        if (step + PF < NSTEP) {               // refill the freed slot
            const int kk = (step + PF) * 16 + 2 * q;
            wbufA0[cur] = *(const float2*)(WA + kk);
            wbufA1[cur] = *(const float2*)(WA + kk + 8);
            wbufB0[cur] = *(const float2*)(WB + kk);
            wbufB1[cur] = *(const float2*)(WB + kk + 8);
        }

        const int kb = lm_kb + (step & 3) * 32;
        const uint32_t koffsw = (uint32_t)(kb ^ cswz);

#pragma unroll
        for (int tp = 0; tp < 4; ++tp) {
            const uint32_t off = rowoff + (uint32_t)tp * 2048u + koffsw;
            uint32_t bh[4], bl[4];
            ldsm4(bh, hi_base + off);
            ldsm4(bl, lo_base + off);
            mma_bf16(acc[2 * tp],     a_hi, bh[0], bh[1]);
            mma_bf16(acc[2 * tp],     a_hi, bl[0], bl[1]);
            mma_bf16(acc[2 * tp],     a_lo, bh[0], bh[1]);
            mma_bf16(acc[2 * tp + 1], a_hi, bh[2], bh[3]);
            mma_bf16(acc[2 * tp + 1], a_hi, bl[2], bl[3]);
            mma_bf16(acc[2 * tp + 1], a_lo, bh[2], bh[3]);
        }
    }

    // epilogue
    float* base0 = &g_pre[((size_t)ks * N_TOT + m0 + wid * 16 + g) * B_];
    float* base8 = base0 + 8 * B_;
#pragma unroll
    for (int t = 0; t < 8; ++t) {
        *(float2*)(base0 + t * 8 + 2 * q) = make_float2(acc[t][0], acc[t][1]);
        *(float2*)(base8 + t * 8 + 2 * q) = make_float2(acc[t][2], acc[t][3]);
    }
}

// ---------------------------------------------------------------------------
// Gates: one block per h (grid 1024), one gate per thread (tid = g*64 + b).
// Sums 8 K-partials + bias + rank-16 LoRA (float4 loads), smem exchange,
// activations on 64 threads.
// ---------------------------------------------------------------------------
__global__ void __launch_bounds__(256)
gates_kernel(const float* __restrict__ b_x,
             const float* __restrict__ b_h,
             const float* __restrict__ B_x,
             const float* __restrict__ B_h,
             const float* __restrict__ c0,
             float* __restrict__ out,
             int l)
{
    __shared__ float sp[G_][B_ + 1];

    const int h  = blockIdx.x;
    const int gg = threadIdx.x >> 6;
    const int b  = threadIdx.x & 63;

    float s = b_x[(l * G_ + gg) * H_ + h] + b_h[(l * G_ + gg) * H_ + h];

    const float* p = &g_pre[((size_t)gg * H_ + h) * B_ + b];
#pragma unroll
    for (int ks = 0; ks < KS; ++ks)
        s += p[(size_t)ks * N_TOT * B_];

    const float4* Bx4 = (const float4*)(B_x + ((size_t)((l * G_ + gg) * H_) + h) * R_);
    const float4* ux4 = (const float4*)(g_u + ((size_t)(0 * G_ + gg) * B_ + b) * R_);
    const float4* Bh4 = (const float4*)(B_h + ((size_t)((l * G_ + gg) * H_) + h) * R_);
    const float4* uh4 = (const float4*)(g_u + ((size_t)(1 * G_ + gg) * B_ + b) * R_);
#pragma unroll
    for (int j = 0; j < 4; ++j) {
        float4 bx = Bx4[j], ux = ux4[j];
        s += bx.x * ux.x + bx.y * ux.y + bx.z * ux.z + bx.w * ux.w;
        float4 bh = Bh4[j], uh = uh4[j];
        s += bh.x * uh.x + bh.y * uh.y + bh.z * uh.z + bh.w * uh.w;
    }
    sp[gg][b] = s;
    __syncthreads();

    if (threadIdx.x < 64) {
        const int bb = threadIdx.x;
        const float i_t = 1.f / (1.f + expf(-sp[0][bb]));
        const float f_t = 1.f / (1.f + expf(-sp[1][bb]));
        const float g_t = tanhf(sp[2][bb]);
        const float o_t = 1.f / (1.f + expf(-sp[3][bb]));

        const float cv   = c0[(size_t)l * B_ * H_ + (size_t)bb * H_ + h];
        const float cnew = f_t * cv + i_t * g_t;
        const float hnew = o_t * tanhf(cnew);

        const size_t idx = (size_t)bb * H_ + h;
        out[(size_t)B_ * H_ * (1 + l) + idx] = hnew;   // h_t[l]
        out[(size_t)B_ * H_ * (3 + l) + idx] = cnew;   // c_t[l]
        if (l == 1)
            out[idx] = hnew;                           // out == h_t[1]
    }
}

// ---------------------------------------------------------------------------
extern "C" void kernel_launch(void* const* d_in, const int* in_sizes, int n_in,
                              void* d_out, int out_size)
{
    const float* input_seq = (const float*)d_in[0];
    const float* h0        = (const float*)d_in[1];
    const float* c0        = (const float*)d_in[2];
    const float* W_x       = (const float*)d_in[3];
    const float* W_h       = (const float*)d_in[4];
    const float* b_x       = (const float*)d_in[5];
    const float* b_h       = (const float*)d_in[6];
    const float* A_x       = (const float*)d_in[7];
    const float* B_x       = (const float*)d_in[8];
    const float* A_h       = (const float*)d_in[9];
    const float* B_h       = (const float*)d_in[10];
    float* out = (float*)d_out;

    const float* x_last = input_seq + (size_t)(T_ - 1) * B_ * I_;

    for (int l = 0; l < L_; ++l) {
        const float* x = (l == 0) ? x_last : (out + (size_t)B_ * H_);  // h_t[0]

        gemm_mma_kernel<<<dim3(N_TOT / MT, KS), 256>>>(x, h0, W_x, W_h, A_x, A_h, l);
        gates_kernel<<<H_, 256>>>(b_x, b_h, B_x, B_h, c0, out, l);
    }
}

// round 6
// speedup vs baseline: 2.8090x; 1.1626x over previous
#include <cuda_runtime.h>
#include <cuda_bf16.h>
#include <math.h>
#include <stdint.h>

// Problem constants
#define T_  256
#define B_  64
#define I_  1024
#define L_  2
#define G_  4
#define H_  1024
#define R_  16

#define N_TOT  (G_ * H_)
#define K_HALF 1024

// GEMM config: grid (32 M-tiles, 8 k-splits), 256 thr, 2 CTA/SM
#define KS     8
#define KSLICE 256             // K per split
#define MT     128             // M rows per CTA
#define NSTEP  (KSLICE / 16)   // 16 k16 steps
#define PF     3               // W prefetch depth

// Scratch
__device__ float g_pre[KS * N_TOT * B_];   // [ks][m][b]  8 MB
__device__ float g_u[2 * G_ * R_ * B_];    // [src][g][r][b]  (b fast!)

#define SWZ(o) ((o) ^ (((o) >> 3) & 0x70))

__device__ __forceinline__ uint32_t smem_u32(const void* p) {
    uint32_t a;
    asm("{ .reg .u64 t; cvta.to.shared.u64 t, %1; cvt.u32.u64 %0, t; }" : "=r"(a) : "l"(p));
    return a;
}
__device__ __forceinline__ void cvt_hilo(float a, float b, uint32_t& hi, uint32_t& lo) {
    __nv_bfloat162 h = __floats2bfloat162_rn(a, b);
    float ra = a - __bfloat162float(h.x);
    float rb = b - __bfloat162float(h.y);
    __nv_bfloat162 l = __floats2bfloat162_rn(ra, rb);
    hi = *(uint32_t*)&h;
    lo = *(uint32_t*)&l;
}
__device__ __forceinline__ void ldsm4(uint32_t* r, uint32_t addr) {
    asm volatile("ldmatrix.sync.aligned.m8n8.x4.shared.b16 {%0,%1,%2,%3}, [%4];"
                 : "=r"(r[0]), "=r"(r[1]), "=r"(r[2]), "=r"(r[3]) : "r"(addr));
}
__device__ __forceinline__ void mma_bf16(float* d, const uint32_t* a, uint32_t b0, uint32_t b1) {
    asm volatile("mma.sync.aligned.m16n8k16.row.col.f32.bf16.bf16.f32 "
                 "{%0,%1,%2,%3}, {%4,%5,%6,%7}, {%8,%9}, {%0,%1,%2,%3};"
                 : "+f"(d[0]), "+f"(d[1]), "+f"(d[2]), "+f"(d[3])
                 : "r"(a[0]), "r"(a[1]), "r"(a[2]), "r"(a[3]), "r"(b0), "r"(b1));
}

// ---------------------------------------------------------------------------
// Fused kernel: (a) rank-16 LoRA projections (hidden under the W stream),
// (b) HMMA split-K GEMM, bf16 3-term split precision, 3-deep W prefetch.
// ---------------------------------------------------------------------------
__global__ void __launch_bounds__(256, 2)
gemm_mma_kernel(const float* __restrict__ x, const float* __restrict__ h0,
                const float* __restrict__ W_x, const float* __restrict__ W_h,
                const float* __restrict__ A_x, const float* __restrict__ A_h,
                int l)
{
    __shared__ __align__(1024) uint8_t sx_hi[8192];   // x chunk: 64 n x 64 k bf16, SWZ
    __shared__ __align__(1024) uint8_t sx_lo[8192];

    const int tid  = threadIdx.x;
    const int wid  = tid >> 5;
    const int lane = tid & 31;
    const int ks   = blockIdx.y;
    const int m0   = blockIdx.x * MT;

    const float* Wbase;
    const float* vbase;
    int koff;
    if (ks < 4) { Wbase = W_x + (size_t)l * N_TOT * K_HALF; vbase = x;
                  koff = ks * KSLICE; }
    else        { Wbase = W_h + (size_t)l * N_TOT * K_HALF; vbase = h0 + (size_t)l * B_ * H_;
                  koff = (ks - 4) * KSLICE; }

    const int g = lane >> 2;
    const int q = lane & 3;

    const float* WA = Wbase + (size_t)(m0 + wid * 16 + g) * K_HALF + koff;
    const float* WB = WA + 8 * (size_t)K_HALF;

    // -------- issue first PF steps of W loads immediately --------
    float2 wbufA0[PF], wbufA1[PF], wbufB0[PF], wbufB1[PF];
#pragma unroll
    for (int s = 0; s < PF; ++s) {
        const int kk = s * 16 + 2 * q;
        wbufA0[s] = *(const float2*)(WA + kk);
        wbufA1[s] = *(const float2*)(WA + kk + 8);
        wbufB0[s] = *(const float2*)(WB + kk);
        wbufB1[s] = *(const float2*)(WB + kk + 8);
    }

    // -------- LoRA projections (while W loads are in flight) --------
    {
        const uint32_t wg = ((uint32_t)blockIdx.y * 32u + blockIdx.x) * 8u + wid;
#pragma unroll
        for (int t = 0; t < 2; ++t) {
            const uint32_t task = wg * 2u + t;      // 0..4095
            const int src  = task >> 11;
            const int rem  = task & 2047;
            const int gg   = rem >> 9;
            const int rem2 = rem & 511;
            const int b    = rem2 >> 3;
            const int rp   = rem2 & 7;

            const float* vec = (src == 0) ? (x + (size_t)b * I_)
                                          : (h0 + (size_t)l * B_ * H_ + (size_t)b * H_);
            const float* A = ((src == 0) ? A_x : A_h) + ((size_t)(l * G_ + gg)) * R_ * K_HALF;
            const float4* v4 = (const float4*)vec;
            const float4* a0 = (const float4*)(A + (size_t)(rp * 2) * K_HALF);
            const float4* a1 = (const float4*)(A + (size_t)(rp * 2 + 1) * K_HALF);

            float acc0 = 0.f, acc1 = 0.f;
#pragma unroll
            for (int j = 0; j < 8; ++j) {
                const int i4 = j * 32 + lane;
                float4 v = v4[i4];
                float4 a = a0[i4];
                float4 c = a1[i4];
                acc0 += v.x * a.x + v.y * a.y + v.z * a.z + v.w * a.w;
                acc1 += v.x * c.x + v.y * c.y + v.z * c.z + v.w * c.w;
            }
#pragma unroll
            for (int off = 16; off > 0; off >>= 1) {
                acc0 += __shfl_down_sync(0xffffffffu, acc0, off);
                acc1 += __shfl_down_sync(0xffffffffu, acc1, off);
            }
            if (lane == 0) {
                // transposed layout: [src][g][r][b], b fast
                float* u = &g_u[((size_t)(src * G_ + gg) * R_) * B_ + b];
                u[(size_t)(rp * 2) * B_]     = acc0;
                u[(size_t)(rp * 2 + 1) * B_] = acc1;
            }
        }
    }

    // -------- x staging geometry --------
    const int xn = tid >> 2;
    const int xq = tid & 3;
    const float* Xsrc = vbase + (size_t)xn * K_HALF + koff + xq * 16;
    uint32_t st_off[4];
#pragma unroll
    for (int j = 0; j < 4; ++j) {
        uint32_t o = (uint32_t)xn * 128u + (uint32_t)xq * 32u + (uint32_t)j * 8u;
        st_off[j] = SWZ(o);
    }

    // ldmatrix lane geometry
    const int lm_row  = 8 * ((lane >> 4) & 1) + (lane & 7);
    const int lm_kb   = ((lane >> 3) & 1) * 16;
    const int cswz    = (lane & 7) << 4;
    const uint32_t rowoff = (uint32_t)lm_row * 128u;
    const uint32_t hi_base = smem_u32(sx_hi);
    const uint32_t lo_base = smem_u32(sx_lo);

    float acc[8][4];
#pragma unroll
    for (int t = 0; t < 8; ++t)
#pragma unroll
        for (int j = 0; j < 4; ++j) acc[t][j] = 0.f;

#pragma unroll
    for (int step = 0; step < NSTEP; ++step) {
        if ((step & 3) == 0) {                 // stage next 64-k chunk of x
            if (step) __syncthreads();
            const float4* s4 = (const float4*)(Xsrc + (step >> 2) * 64);
#pragma unroll
            for (int j = 0; j < 4; ++j) {
                float4 f = s4[j];
                uint32_t h01, l01, h23, l23;
                cvt_hilo(f.x, f.y, h01, l01);
                cvt_hilo(f.z, f.w, h23, l23);
                *(uint2*)(sx_hi + st_off[j]) = make_uint2(h01, h23);
                *(uint2*)(sx_lo + st_off[j]) = make_uint2(l01, l23);
            }
            __syncthreads();
        }

        const int cur = step % PF;             // static under full unroll

        uint32_t a_hi[4], a_lo[4];
        cvt_hilo(wbufA0[cur].x, wbufA0[cur].y, a_hi[0], a_lo[0]);
        cvt_hilo(wbufB0[cur].x, wbufB0[cur].y, a_hi[1], a_lo[1]);
        cvt_hilo(wbufA1[cur].x, wbufA1[cur].y, a_hi[2], a_lo[2]);
        cvt_hilo(wbufB1[cur].x, wbufB1[cur].y, a_hi[3], a_lo[3]);

        if (step + PF < NSTEP) {               // refill the freed slot
            const int kk = (step + PF) * 16 + 2 * q;
            wbufA0[cur] = *(const float2*)(WA + kk);
            wbufA1[cur] = *(const float2*)(WA + kk + 8);
            wbufB0[cur] = *(const float2*)(WB + kk);
            wbufB1[cur] = *(const float2*)(WB + kk + 8);
        }

        const int kb = lm_kb + (step & 3) * 32;
        const uint32_t koffsw = (uint32_t)(kb ^ cswz);

#pragma unroll
        for (int tp = 0; tp < 4; ++tp) {
            const uint32_t off = rowoff + (uint32_t)tp * 2048u + koffsw;
            uint32_t bh[4], bl[4];
            ldsm4(bh, hi_base + off);
            ldsm4(bl, lo_base + off);
            mma_bf16(acc[2 * tp],     a_hi, bh[0], bh[1]);
            mma_bf16(acc[2 * tp],     a_hi, bl[0], bl[1]);
            mma_bf16(acc[2 * tp],     a_lo, bh[0], bh[1]);
            mma_bf16(acc[2 * tp + 1], a_hi, bh[2], bh[3]);
            mma_bf16(acc[2 * tp + 1], a_hi, bl[2], bl[3]);
            mma_bf16(acc[2 * tp + 1], a_lo, bh[2], bh[3]);
        }
    }

    // epilogue
    float* base0 = &g_pre[((size_t)ks * N_TOT + m0 + wid * 16 + g) * B_];
    float* base8 = base0 + 8 * B_;
#pragma unroll
    for (int t = 0; t < 8; ++t) {
        *(float2*)(base0 + t * 8 + 2 * q) = make_float2(acc[t][0], acc[t][1]);
        *(float2*)(base8 + t * 8 + 2 * q) = make_float2(acc[t][2], acc[t][3]);
    }
}

// ---------------------------------------------------------------------------
// Gates: one block per h (grid 1024), one gate per thread (tid = g*64 + b).
// g_pre partials coalesced (b fast); LoRA-B vectors broadcast per (g,h);
// g_u coalesced (b fast). smem exchange, activations on 64-thread tail.
// ---------------------------------------------------------------------------
__global__ void __launch_bounds__(256)
gates_kernel(const float* __restrict__ b_x,
             const float* __restrict__ b_h,
             const float* __restrict__ B_x,
             const float* __restrict__ B_h,
             const float* __restrict__ c0,
             float* __restrict__ out,
             int l)
{
    __shared__ float sp[G_][B_ + 1];

    const int h  = blockIdx.x;
    const int gg = threadIdx.x >> 6;
    const int b  = threadIdx.x & 63;

    float s = b_x[(l * G_ + gg) * H_ + h] + b_h[(l * G_ + gg) * H_ + h];

    const float* p = &g_pre[((size_t)gg * H_ + h) * B_ + b];
#pragma unroll
    for (int ks = 0; ks < KS; ++ks)
        s += p[(size_t)ks * N_TOT * B_];

    // LoRA: Bx[r] is uniform across the 64-thread group (broadcast loads);
    // u[r*64+b] is lane-coalesced.
    const float* Bx = B_x + ((size_t)((l * G_ + gg) * H_) + h) * R_;
    const float* Bh = B_h + ((size_t)((l * G_ + gg) * H_) + h) * R_;
    const float* ux = g_u + ((size_t)(0 * G_ + gg) * R_) * B_ + b;
    const float* uh = g_u + ((size_t)(1 * G_ + gg) * R_) * B_ + b;
#pragma unroll
    for (int r = 0; r < R_; ++r)
        s += Bx[r] * ux[(size_t)r * B_];
#pragma unroll
    for (int r = 0; r < R_; ++r)
        s += Bh[r] * uh[(size_t)r * B_];

    sp[gg][b] = s;
    __syncthreads();

    if (threadIdx.x < 64) {
        const int bb = threadIdx.x;
        const float i_t = 1.f / (1.f + expf(-sp[0][bb]));
        const float f_t = 1.f / (1.f + expf(-sp[1][bb]));
        const float g_t = tanhf(sp[2][bb]);
        const float o_t = 1.f / (1.f + expf(-sp[3][bb]));

        const float cv   = c0[(size_t)l * B_ * H_ + (size_t)bb * H_ + h];
        const float cnew = f_t * cv + i_t * g_t;
        const float hnew = o_t * tanhf(cnew);

        const size_t idx = (size_t)bb * H_ + h;
        out[(size_t)B_ * H_ * (1 + l) + idx] = hnew;   // h_t[l]
        out[(size_t)B_ * H_ * (3 + l) + idx] = cnew;   // c_t[l]
        if (l == 1)
            out[idx] = hnew;                           // out == h_t[1]
    }
}

// ---------------------------------------------------------------------------
extern "C" void kernel_launch(void* const* d_in, const int* in_sizes, int n_in,
                              void* d_out, int out_size)
{
    const float* input_seq = (const float*)d_in[0];
    const float* h0        = (const float*)d_in[1];
    const float* c0        = (const float*)d_in[2];
    const float* W_x       = (const float*)d_in[3];
    const float* W_h       = (const float*)d_in[4];
    const float* b_x       = (const float*)d_in[5];
    const float* b_h       = (const float*)d_in[6];
    const float* A_x       = (const float*)d_in[7];
    const float* B_x       = (const float*)d_in[8];
    const float* A_h       = (const float*)d_in[9];
    const float* B_h       = (const float*)d_in[10];
    float* out = (float*)d_out;

    const float* x_last = input_seq + (size_t)(T_ - 1) * B_ * I_;

    for (int l = 0; l < L_; ++l) {
        const float* x = (l == 0) ? x_last : (out + (size_t)B_ * H_);  // h_t[0]

        gemm_mma_kernel<<<dim3(N_TOT / MT, KS), 256>>>(x, h0, W_x, W_h, A_x, A_h, l);
        gates_kernel<<<H_, 256>>>(b_x, b_h, B_x, B_h, c0, out, l);
    }
}